// round 8
// baseline (speedup 1.0000x reference)
#include <cuda_runtime.h>
#include <math.h>

// Problem constants
#define BB 2
#define NN 2048
#define BN 4096          // B*N
#define CC 256
#define HI 64
#define WI 176
#define HW (HI*WI)       // 11264
#define TS 16            // tile size
#define TBX (WI/TS)      // 11
#define TBY (HI/TS)      // 4
#define TPB (TBX*TBY)    // 44 tiles per batch
#define NT (BB*TPB)      // 88 tiles total
#define MAXG 2048
#define FM_SIZE (BB*CC*HW)
#define NSL 8            // channel slices in render
#define CPS 32           // channels per slice

typedef unsigned long long u64;

// ---- f32x2 packed FMA helpers (sm_103a) ----
__device__ __forceinline__ void fma2(u64 &acc, u64 a, u64 b) {
    asm("fma.rn.f32x2 %0, %1, %2, %0;" : "+l"(acc) : "l"(a), "l"(b));
}
__device__ __forceinline__ u64 pk2(float lo, float hi) {
    u64 r; asm("mov.b64 %0, {%1, %2};" : "=l"(r) : "f"(lo), "f"(hi)); return r;
}
__device__ __forceinline__ float2 upk(u64 v) {
    float2 r; asm("mov.b64 {%0, %1}, %2;" : "=f"(r.x), "=f"(r.y) : "l"(v)); return r;
}

// ---------------- device scratch ----------------
__device__ float g_h1[BN*64];
__device__ float g_h2[BN*128];
__device__ float g_feats[BN*CC];
__device__ float g_ft1[BN*CC];
__device__ float g_featsT[BN*CC];

__device__ float g_px[BN], g_py[BN], g_isx[BN], g_isy[BN], g_w[BN], g_as[BN];
__device__ int   g_tcount[NT];
__device__ int   g_tlist[NT*MAXG];

// ---------------- projection + binning (fused) ----------------
__global__ void proj_bin_kernel(const float* __restrict__ g, const float* __restrict__ Kin) {
    int i = blockIdx.x * blockDim.x + threadIdx.x;
    if (i >= BN) return;
    const float* gd = g + (size_t)i * 14;
    float x = gd[0], y = gd[1], z = gd[2];
    float k00 = Kin[0], k01 = Kin[1], k02 = Kin[2];
    float k10 = Kin[3], k11 = Kin[4], k12 = Kin[5];
    float k20 = Kin[6], k21 = Kin[7], k22 = Kin[8];
    float pz = k20 * x + k21 * y + k22 * z;
    float denom = pz + 1e-6f;
    float pxn = (k00 * x + k01 * y + k02 * z) / denom;
    float pyn = (k10 * x + k11 * y + k12 * z) / denom;
    float scale_x = (float)WI / k02 * 0.5f;
    float scale_y = (float)HI / k12 * 0.5f;
    float px = pxn * scale_x;
    float py = pyn * scale_y;
    bool valid = (z > 0.1f);
    bool inb = (px >= 0.f) && (px < (float)WI) && (py >= 0.f) && (py < (float)HI);
    bool mask = valid && inb;
    float sx = fmaxf(gd[5] * scale_x, 1.0f);
    float sy = fmaxf(gd[6] * scale_y, 1.0f);
    float w = mask ? gd[12] : 0.0f;
    g_px[i] = px;  g_py[i] = py;
    g_isx[i] = 1.0f / sx;  g_isy[i] = 1.0f / sy;
    g_w[i]  = w;
    g_as[i] = 0.5f * (sx + sy);
    if (w == 0.0f) return;

    float rx = 3.0f * sx;
    float ry = 3.0f * sy;
    int b = i >> 11;
    int tx0 = max(0, (int)floorf((px - rx) * (1.0f / TS)));
    int tx1 = min(TBX - 1, (int)floorf((px + rx) * (1.0f / TS)));
    int ty0 = max(0, (int)floorf((py - ry) * (1.0f / TS)));
    int ty1 = min(TBY - 1, (int)floorf((py + ry) * (1.0f / TS)));
    for (int ty = ty0; ty <= ty1; ty++)
        for (int tx = tx0; tx <= tx1; tx++) {
            int t = b * TPB + ty * TBX + tx;
            int o = atomicAdd(&g_tcount[t], 1);
            if (o < MAXG) g_tlist[t * MAXG + o] = i;
        }
}

// ---------------- fp32 GEMM with FFMA2, conflict-free dup layout ----------------
// C = act(A[MxK] @ W[KxN] + b). 64x64 tile, K-tile 16, 256 threads.
// Thread (txq=t&15, tyq=t>>4) computes M rows tyq*4..+3 (2 f32x2 pairs, natural
// from LDS.128 of transposed A) x N cols {2txq,2txq+1,2txq+32,2txq+33} (dup
// pairs in smem, LDS.128 at txq*16B -> conflict-free).
__global__ void __launch_bounds__(256) gemm_kernel(
    const float* __restrict__ A, const float* __restrict__ Wm,
    const float* __restrict__ bias, float* __restrict__ Cm,
    int Kd, int Nd, int doRelu)
{
    __shared__ __align__(16) float As[16][68];   // [k][m], row 272B
    __shared__ __align__(16) u64   Bd[16][64];   // [k][n] dup pairs, row 512B
    int m0 = blockIdx.x * 64;
    int n0 = blockIdx.y * 64;
    int t = threadIdx.x;
    int txq = t & 15;
    int tyq = t >> 4;
    u64 acc[2][4];
    #pragma unroll
    for (int i = 0; i < 2; i++)
        #pragma unroll
        for (int j = 0; j < 4; j++) acc[i][j] = 0ull;

    bool fast = ((Kd & 15) == 0);
    for (int k0 = 0; k0 < Kd; k0 += 16) {
        if (fast) {
            int mr = t >> 2, kq = (t & 3) * 4;
            float4 a4 = *(const float4*)&A[(size_t)(m0 + mr) * Kd + k0 + kq];
            As[kq + 0][mr] = a4.x; As[kq + 1][mr] = a4.y;
            As[kq + 2][mr] = a4.z; As[kq + 3][mr] = a4.w;
            int kk = t >> 4, j4 = (t & 15) * 4;
            float4 w4 = *(const float4*)&Wm[(size_t)(k0 + kk) * Nd + n0 + j4];
            ulonglong2 lo; lo.x = pk2(w4.x, w4.x); lo.y = pk2(w4.y, w4.y);
            ulonglong2 hi; hi.x = pk2(w4.z, w4.z); hi.y = pk2(w4.w, w4.w);
            *(ulonglong2*)&Bd[kk][j4]     = lo;
            *(ulonglong2*)&Bd[kk][j4 + 2] = hi;
        } else {
            int r = t >> 4, c = t & 15;
            #pragma unroll
            for (int it = 0; it < 4; it++) {
                int k = k0 + c;
                As[c][r + it * 16] = (k < Kd) ? A[(size_t)(m0 + r + it * 16) * Kd + k] : 0.f;
            }
            int kk = t >> 6, j = t & 63;
            #pragma unroll
            for (int it = 0; it < 4; it++) {
                int k = k0 + kk + it * 4;
                float w = (k < Kd) ? Wm[(size_t)k * Nd + n0 + j] : 0.f;
                Bd[kk + it * 4][j] = pk2(w, w);
            }
        }
        __syncthreads();
        #pragma unroll
        for (int kk = 0; kk < 16; kk++) {
            ulonglong2 ap  = *(const ulonglong2*)&As[kk][tyq * 4];       // rows pairs
            ulonglong2 blo = *(const ulonglong2*)&Bd[kk][2 * txq];       // cols 2q,2q+1
            ulonglong2 bhi = *(const ulonglong2*)&Bd[kk][32 + 2 * txq];  // cols +32
            fma2(acc[0][0], ap.x, blo.x); fma2(acc[0][1], ap.x, blo.y);
            fma2(acc[0][2], ap.x, bhi.x); fma2(acc[0][3], ap.x, bhi.y);
            fma2(acc[1][0], ap.y, blo.x); fma2(acc[1][1], ap.y, blo.y);
            fma2(acc[1][2], ap.y, bhi.x); fma2(acc[1][3], ap.y, bhi.y);
        }
        __syncthreads();
    }
    float2 bvlo = *(const float2*)&bias[n0 + 2 * txq];
    float2 bvhi = *(const float2*)&bias[n0 + 32 + 2 * txq];
    #pragma unroll
    for (int mp = 0; mp < 2; mp++) {
        float2 c0 = upk(acc[mp][0]), c1 = upk(acc[mp][1]);
        float2 c2 = upk(acc[mp][2]), c3 = upk(acc[mp][3]);
        int r0 = m0 + tyq * 4 + mp * 2;
        float2 lo0 = make_float2(c0.x + bvlo.x, c1.x + bvlo.y);
        float2 hi0 = make_float2(c2.x + bvhi.x, c3.x + bvhi.y);
        float2 lo1 = make_float2(c0.y + bvlo.x, c1.y + bvlo.y);
        float2 hi1 = make_float2(c2.y + bvhi.x, c3.y + bvhi.y);
        if (doRelu) {
            lo0.x = fmaxf(lo0.x, 0.f); lo0.y = fmaxf(lo0.y, 0.f);
            hi0.x = fmaxf(hi0.x, 0.f); hi0.y = fmaxf(hi0.y, 0.f);
            lo1.x = fmaxf(lo1.x, 0.f); lo1.y = fmaxf(lo1.y, 0.f);
            hi1.x = fmaxf(hi1.x, 0.f); hi1.y = fmaxf(hi1.y, 0.f);
        }
        *(float2*)&Cm[(size_t)r0 * Nd + n0 + 2 * txq]            = lo0;
        *(float2*)&Cm[(size_t)r0 * Nd + n0 + 32 + 2 * txq]       = hi0;
        *(float2*)&Cm[(size_t)(r0 + 1) * Nd + n0 + 2 * txq]      = lo1;
        *(float2*)&Cm[(size_t)(r0 + 1) * Nd + n0 + 32 + 2 * txq] = hi1;
    }
}

// ---------------- tile render: FFMA2 feature loop, fused normalization ------
// grid (NT, 8), 256 threads. Roles:
//  - gw/density: pixel t (lx=t&15, ly=t>>4)
//  - accumulate: chg=t&7 -> channels {2chg,2chg+1,16+2chg,17+2chg} of the
//    32-ch slice; pr=t>>3 -> pixels pbase=pr*8 .. +7 (4 f32x2 pairs).
__global__ void __launch_bounds__(256, 2) render_kernel(float* __restrict__ out) {
    int tile = blockIdx.x;
    int slice = blockIdx.y;
    int b = tile / TPB;
    int tl = tile % TPB;
    int tx0 = (tl % TBX) * TS;
    int ty0 = (tl / TBX) * TS;
    int t = threadIdx.x;
    int lx = t & 15;
    int ly = t >> 4;
    int chg = t & 7;
    int pr = t >> 3;
    int prow = pr >> 1;
    int phalf = pr & 1;
    const int pbase = pr * 8;

    __shared__ float s_px[16], s_py[16], s_isx[16], s_isy[16], s_w[16], s_as[16];
    __shared__ int   s_n[16];
    __shared__ float s_ex[16][16], s_ey[16][16], s_dx2[16][16], s_dy2[16][16];
    __shared__ __align__(16) float s_gw[16][256];
    __shared__ __align__(16) u64   s_Fd[16][CPS];   // dup pairs
    __shared__ float s_d[256];

    u64 acc[4][4];   // 4 channels x 4 pixel-pairs
    #pragma unroll
    for (int i = 0; i < 4; i++)
        #pragma unroll
        for (int p = 0; p < 4; p++) acc[i][p] = 0ull;
    float dacc = 0.f, uacc = 0.f;

    int K = g_tcount[tile];
    if (K > MAXG) K = MAXG;

    for (int c0 = 0; c0 < K; c0 += 16) {
        if (t < 16) {
            int idx = c0 + t;
            if (idx < K) {
                int n = g_tlist[tile * MAXG + idx];
                s_n[t] = n;
                s_px[t] = g_px[n];   s_py[t] = g_py[n];
                s_isx[t] = g_isx[n]; s_isy[t] = g_isy[n];
                s_w[t] = g_w[n];     s_as[t] = g_as[n];
            } else {
                s_n[t] = 0;
                s_px[t] = 3e8f; s_py[t] = 3e8f;
                s_isx[t] = 1.f; s_isy[t] = 1.f;
                s_w[t] = 0.f;   s_as[t] = 0.f;
            }
        }
        __syncthreads();
        // feats slice: 16 gaussians x 32 channels as dup pairs
        if (t < 128) {
            int j = t >> 3;
            int ci = (t & 7) * 4;
            int n = s_n[j];
            float4 f = *(const float4*)&g_featsT[(size_t)n * CC + slice * CPS + ci];
            ulonglong2 lo; lo.x = pk2(f.x, f.x); lo.y = pk2(f.y, f.y);
            ulonglong2 hi; hi.x = pk2(f.z, f.z); hi.y = pk2(f.w, f.w);
            *(ulonglong2*)&s_Fd[j][ci]     = lo;
            *(ulonglong2*)&s_Fd[j][ci + 2] = hi;
        }
        // separable exp
        {
            int j = t >> 4, i2 = t & 15;
            float dx = ((float)(tx0 + i2) - s_px[j]) * s_isx[j];
            float dx2 = dx * dx;
            s_dx2[j][i2] = dx2;
            s_ex[j][i2] = __expf(-0.5f * dx2);
            float dy = ((float)(ty0 + i2) - s_py[j]) * s_isy[j];
            float dy2 = dy * dy;
            s_dy2[j][i2] = dy2;
            s_ey[j][i2] = __expf(-0.5f * dy2);
        }
        __syncthreads();
        // gw for my pixel across 16 gaussians + density/uncertainty
        #pragma unroll
        for (int j = 0; j < 16; j++) {
            float d = s_dx2[j][lx] + s_dy2[j][ly];
            float gwv = (d < 9.0f) ? s_w[j] * s_ex[j][lx] * s_ey[j][ly] : 0.0f;
            s_gw[j][t] = gwv;
            dacc += gwv;
            uacc += gwv * s_as[j];
        }
        __syncthreads();
        // feature accumulate: 16 FFMA2 per gaussian
        #pragma unroll
        for (int j = 0; j < 16; j++) {
            ulonglong2 f01 = *(const ulonglong2*)&s_Fd[j][2 * chg];       // ch 2q,2q+1
            ulonglong2 f23 = *(const ulonglong2*)&s_Fd[j][16 + 2 * chg];  // ch +16
            const ulonglong2* gp = (const ulonglong2*)&s_gw[j][pbase];
            ulonglong2 g01 = gp[0];
            ulonglong2 g23 = gp[1];
            fma2(acc[0][0], f01.x, g01.x); fma2(acc[0][1], f01.x, g01.y);
            fma2(acc[0][2], f01.x, g23.x); fma2(acc[0][3], f01.x, g23.y);
            fma2(acc[1][0], f01.y, g01.x); fma2(acc[1][1], f01.y, g01.y);
            fma2(acc[1][2], f01.y, g23.x); fma2(acc[1][3], f01.y, g23.y);
            fma2(acc[2][0], f23.x, g01.x); fma2(acc[2][1], f23.x, g01.y);
            fma2(acc[2][2], f23.x, g23.x); fma2(acc[2][3], f23.x, g23.y);
            fma2(acc[3][0], f23.y, g01.x); fma2(acc[3][1], f23.y, g01.y);
            fma2(acc[3][2], f23.y, g23.x); fma2(acc[3][3], f23.y, g23.y);
        }
        __syncthreads();
    }

    // share density, normalize, write
    s_d[t] = dacc;
    __syncthreads();
    float inv[8];
    #pragma unroll
    for (int p = 0; p < 8; p++) inv[p] = 1.0f / fmaxf(s_d[pbase + p], 1e-6f);

    int gy = ty0 + prow;
    #pragma unroll
    for (int ci = 0; ci < 4; ci++) {
        int ch = slice * CPS + ((ci < 2) ? (2 * chg + ci) : (16 + 2 * chg + ci - 2));
        float* row = out + (((size_t)(b * CC + ch) * HI + gy) * WI + tx0 + phalf * 8);
        float2 v0 = upk(acc[ci][0]);
        float2 v1 = upk(acc[ci][1]);
        float2 v2 = upk(acc[ci][2]);
        float2 v3 = upk(acc[ci][3]);
        float4 o0 = make_float4(v0.x * inv[0], v0.y * inv[1], v1.x * inv[2], v1.y * inv[3]);
        float4 o1 = make_float4(v2.x * inv[4], v2.y * inv[5], v3.x * inv[6], v3.y * inv[7]);
        *(float4*)&row[0] = o0;
        *(float4*)&row[4] = o1;
    }
    if (slice == 0) {
        int pix = (ty0 + ly) * WI + tx0 + lx;
        float d = fmaxf(dacc, 1e-6f);
        out[FM_SIZE + b * HW + pix] = uacc / d;        // uncertainty / density
        out[FM_SIZE + BB * HW + b * HW + pix] = d;     // clipped density
    }
}

// ---------------- launch ----------------
extern "C" void kernel_launch(void* const* d_in, const int* in_sizes, int n_in,
                              void* d_out, int out_size) {
    const float* g      = (const float*)d_in[0];
    const float* intr   = (const float*)d_in[1];
    const float* enc_w1 = (const float*)d_in[2];
    const float* enc_b1 = (const float*)d_in[3];
    const float* enc_w2 = (const float*)d_in[4];
    const float* enc_b2 = (const float*)d_in[5];
    const float* enc_w3 = (const float*)d_in[6];
    const float* enc_b3 = (const float*)d_in[7];
    const float* ft_w1  = (const float*)d_in[8];
    const float* ft_b1  = (const float*)d_in[9];
    const float* ft_w2  = (const float*)d_in[10];
    const float* ft_b2  = (const float*)d_in[11];
    float* out = (float*)d_out;

    float *p_h1, *p_h2, *p_feats, *p_ft1, *p_featsT;
    int* p_tcount;
    cudaGetSymbolAddress((void**)&p_h1, g_h1);
    cudaGetSymbolAddress((void**)&p_h2, g_h2);
    cudaGetSymbolAddress((void**)&p_feats, g_feats);
    cudaGetSymbolAddress((void**)&p_ft1, g_ft1);
    cudaGetSymbolAddress((void**)&p_featsT, g_featsT);
    cudaGetSymbolAddress((void**)&p_tcount, g_tcount);

    cudaMemsetAsync(p_tcount, 0, NT * sizeof(int));
    proj_bin_kernel<<<(BN + 255) / 256, 256>>>(g, intr);

    gemm_kernel<<<dim3(BN / 64, 1), 256>>>(g,        enc_w1, enc_b1, p_h1,     14,  64,  1);
    gemm_kernel<<<dim3(BN / 64, 2), 256>>>(p_h1,     enc_w2, enc_b2, p_h2,     64,  128, 1);
    gemm_kernel<<<dim3(BN / 64, 4), 256>>>(p_h2,     enc_w3, enc_b3, p_feats,  128, 256, 0);
    gemm_kernel<<<dim3(BN / 64, 4), 256>>>(p_feats,  ft_w1,  ft_b1,  p_ft1,    256, 256, 1);
    gemm_kernel<<<dim3(BN / 64, 4), 256>>>(p_ft1,    ft_w2,  ft_b2,  p_featsT, 256, 256, 0);

    render_kernel<<<dim3(NT, NSL), 256>>>(out);
}

// round 9
// speedup vs baseline: 1.1685x; 1.1685x over previous
#include <cuda_runtime.h>
#include <math.h>

// Problem constants
#define BB 2
#define NN 2048
#define BN 4096          // B*N
#define CC 256
#define HI 64
#define WI 176
#define HW (HI*WI)       // 11264
#define TS 16            // tile size
#define TBX (WI/TS)      // 11
#define TBY (HI/TS)      // 4
#define TPB (TBX*TBY)    // 44 tiles per batch
#define NT (BB*TPB)      // 88 tiles total
#define MAXG 2048
#define FM_SIZE (BB*CC*HW)

// ---------------- device scratch ----------------
__device__ float g_h1[BN*64];
__device__ float g_h2[BN*128];
__device__ float g_feats[BN*CC];
__device__ float g_ft1[BN*CC];
__device__ float g_featsT[BN*CC];

__device__ float g_px[BN], g_py[BN], g_isx[BN], g_isy[BN], g_w[BN], g_as[BN];
__device__ int   g_tcount[NT];
__device__ int   g_tlist[NT*MAXG];

// ---------------- projection + binning (fused) ----------------
__global__ void proj_bin_kernel(const float* __restrict__ g, const float* __restrict__ Kin) {
    int i = blockIdx.x * blockDim.x + threadIdx.x;
    if (i >= BN) return;
    const float* gd = g + (size_t)i * 14;
    float x = gd[0], y = gd[1], z = gd[2];
    float k00 = Kin[0], k01 = Kin[1], k02 = Kin[2];
    float k10 = Kin[3], k11 = Kin[4], k12 = Kin[5];
    float k20 = Kin[6], k21 = Kin[7], k22 = Kin[8];
    float pz = k20 * x + k21 * y + k22 * z;
    float denom = pz + 1e-6f;
    float pxn = (k00 * x + k01 * y + k02 * z) / denom;
    float pyn = (k10 * x + k11 * y + k12 * z) / denom;
    float scale_x = (float)WI / k02 * 0.5f;
    float scale_y = (float)HI / k12 * 0.5f;
    float px = pxn * scale_x;
    float py = pyn * scale_y;
    bool valid = (z > 0.1f);
    bool inb = (px >= 0.f) && (px < (float)WI) && (py >= 0.f) && (py < (float)HI);
    bool mask = valid && inb;
    float sx = fmaxf(gd[5] * scale_x, 1.0f);
    float sy = fmaxf(gd[6] * scale_y, 1.0f);
    float w = mask ? gd[12] : 0.0f;
    g_px[i] = px;  g_py[i] = py;
    g_isx[i] = 1.0f / sx;  g_isy[i] = 1.0f / sy;
    g_w[i]  = w;
    g_as[i] = 0.5f * (sx + sy);
    if (w == 0.0f) return;

    float rx = 3.0f * sx;
    float ry = 3.0f * sy;
    int b = i >> 11;
    int tx0 = max(0, (int)floorf((px - rx) * (1.0f / TS)));
    int tx1 = min(TBX - 1, (int)floorf((px + rx) * (1.0f / TS)));
    int ty0 = max(0, (int)floorf((py - ry) * (1.0f / TS)));
    int ty1 = min(TBY - 1, (int)floorf((py + ry) * (1.0f / TS)));
    for (int ty = ty0; ty <= ty1; ty++)
        for (int tx = tx0; tx <= tx1; tx++) {
            int t = b * TPB + ty * TBX + tx;
            int o = atomicAdd(&g_tcount[t], 1);
            if (o < MAXG) g_tlist[t * MAXG + o] = i;
        }
}

// ---------------- fp32 GEMM: 64x64 tile, 512 threads, 2x4 microtile ----------
// C = act(A[MxK] @ W[KxN] + b). Doubled warps per block for latency hiding:
// inner step = 1 LDS.64 (A pair) + 1 LDS.128 (B quad) + 8 FFMA.
__global__ void __launch_bounds__(512) gemm_kernel(
    const float* __restrict__ A, const float* __restrict__ Wm,
    const float* __restrict__ bias, float* __restrict__ Cm,
    int Kd, int Nd, int doRelu)
{
    __shared__ __align__(16) float As[16][66];   // [k][m], row 264B
    __shared__ __align__(16) float Bs[16][64];   // [k][n], row 256B
    int m0 = blockIdx.x * 64;
    int n0 = blockIdx.y * 64;
    int t = threadIdx.x;
    int txq = t & 15;        // N group of 4
    int tyq = t >> 4;        // 0..31 -> M pair (2 rows)
    float acc[2][4];
    #pragma unroll
    for (int i = 0; i < 2; i++)
        #pragma unroll
        for (int j = 0; j < 4; j++) acc[i][j] = 0.f;

    bool fast = ((Kd & 15) == 0);
    for (int k0 = 0; k0 < Kd; k0 += 16) {
        if (fast) {
            // A tile: 1024 elems / 512 thr = one float2 each, stored transposed
            int mr = t >> 3, kq = (t & 7) * 2;
            float2 a2 = *(const float2*)&A[(size_t)(m0 + mr) * Kd + k0 + kq];
            As[kq][mr]     = a2.x;
            As[kq + 1][mr] = a2.y;
            // B tile: one float2 each
            int kk = t >> 5, j2 = (t & 31) * 2;
            float2 w2 = *(const float2*)&Wm[(size_t)(k0 + kk) * Nd + n0 + j2];
            *(float2*)&Bs[kk][j2] = w2;
        } else {
            // guarded scalar path (only the K=14 layer)
            #pragma unroll
            for (int it = 0; it < 2; it++) {
                int idx = t + it * 512;
                int m = idx & 63, c = idx >> 6;
                int k = k0 + c;
                As[c][m] = (k < Kd) ? A[(size_t)(m0 + m) * Kd + k] : 0.f;
                int j = idx & 63, kk = idx >> 6;
                Bs[kk][j] = (k0 + kk < Kd) ? Wm[(size_t)(k0 + kk) * Nd + n0 + j] : 0.f;
            }
        }
        __syncthreads();
        #pragma unroll
        for (int kk = 0; kk < 16; kk++) {
            float2 ap = *(const float2*)&As[kk][tyq * 2];
            float4 bq = *(const float4*)&Bs[kk][txq * 4];
            acc[0][0] += ap.x * bq.x; acc[0][1] += ap.x * bq.y;
            acc[0][2] += ap.x * bq.z; acc[0][3] += ap.x * bq.w;
            acc[1][0] += ap.y * bq.x; acc[1][1] += ap.y * bq.y;
            acc[1][2] += ap.y * bq.z; acc[1][3] += ap.y * bq.w;
        }
        __syncthreads();
    }
    float4 bv = *(const float4*)&bias[n0 + txq * 4];
    #pragma unroll
    for (int i = 0; i < 2; i++) {
        float4 o;
        o.x = acc[i][0] + bv.x; o.y = acc[i][1] + bv.y;
        o.z = acc[i][2] + bv.z; o.w = acc[i][3] + bv.w;
        if (doRelu) {
            o.x = fmaxf(o.x, 0.f); o.y = fmaxf(o.y, 0.f);
            o.z = fmaxf(o.z, 0.f); o.w = fmaxf(o.w, 0.f);
        }
        *(float4*)&Cm[(size_t)(m0 + tyq * 2 + i) * Nd + n0 + txq * 4] = o;
    }
}

// ---------------- tile render: 4 slices x 64 ch, fused normalization ---------
// grid (NT, 4), 256 threads. Thread owns pixel t for gw/density, and
// (channels lx*4..+3 of slice, pixel row ly) for feature accumulation.
__global__ void __launch_bounds__(256, 2) render_kernel(float* __restrict__ out) {
    int tile = blockIdx.x;
    int slice = blockIdx.y;
    int b = tile / TPB;
    int tl = tile % TPB;
    int tx0 = (tl % TBX) * TS;
    int ty0 = (tl / TBX) * TS;
    int t = threadIdx.x;
    int lx = t & 15;
    int ly = t >> 4;

    __shared__ float s_px[16], s_py[16], s_isx[16], s_isy[16], s_w[16], s_as[16];
    __shared__ int   s_n[16];
    __shared__ float s_ex[16][16], s_ey[16][16], s_dx2[16][16], s_dy2[16][16];
    __shared__ __align__(16) float s_gw[16][256];
    __shared__ __align__(16) float s_F[16][64];
    __shared__ float s_d[256];

    float acc[4][16];
    #pragma unroll
    for (int i = 0; i < 4; i++)
        #pragma unroll
        for (int p = 0; p < 16; p++) acc[i][p] = 0.f;
    float dacc = 0.f, uacc = 0.f;

    int K = g_tcount[tile];
    if (K > MAXG) K = MAXG;

    for (int c0 = 0; c0 < K; c0 += 16) {
        if (t < 16) {
            int idx = c0 + t;
            if (idx < K) {
                int n = g_tlist[tile * MAXG + idx];
                s_n[t] = n;
                s_px[t] = g_px[n];   s_py[t] = g_py[n];
                s_isx[t] = g_isx[n]; s_isy[t] = g_isy[n];
                s_w[t] = g_w[n];     s_as[t] = g_as[n];
            } else {
                s_n[t] = 0;
                s_px[t] = 3e8f; s_py[t] = 3e8f;
                s_isx[t] = 1.f; s_isy[t] = 1.f;
                s_w[t] = 0.f;   s_as[t] = 0.f;
            }
        }
        __syncthreads();
        // feats slice: 16 gaussians x 64 channels (one float4 per thread)
        {
            int j = t >> 4;
            int cc = (t & 15) * 4;
            int n = s_n[j];
            float4 f = *(const float4*)&g_featsT[(size_t)n * CC + slice * 64 + cc];
            *(float4*)&s_F[j][cc] = f;
        }
        // separable exp
        {
            int j = t >> 4, i2 = t & 15;
            float dx = ((float)(tx0 + i2) - s_px[j]) * s_isx[j];
            float dx2 = dx * dx;
            s_dx2[j][i2] = dx2;
            s_ex[j][i2] = __expf(-0.5f * dx2);
            float dy = ((float)(ty0 + i2) - s_py[j]) * s_isy[j];
            float dy2 = dy * dy;
            s_dy2[j][i2] = dy2;
            s_ey[j][i2] = __expf(-0.5f * dy2);
        }
        __syncthreads();
        // gw for my pixel across 16 gaussians + density/uncertainty
        #pragma unroll
        for (int j = 0; j < 16; j++) {
            float d = s_dx2[j][lx] + s_dy2[j][ly];
            float gwv = (d < 9.0f) ? s_w[j] * s_ex[j][lx] * s_ey[j][ly] : 0.0f;
            s_gw[j][t] = gwv;
            dacc += gwv;
            uacc += gwv * s_as[j];
        }
        __syncthreads();
        // feature accumulate: acc[ci][pp] += F[j][lx*4+ci] * gw[j][ly*16+pp]
        {
            int cg = lx;
            #pragma unroll
            for (int j = 0; j < 16; j++) {
                float4 f = *(const float4*)&s_F[j][cg * 4];
                const float* gwr = &s_gw[j][ly * 16];
                #pragma unroll
                for (int pp = 0; pp < 16; pp += 4) {
                    float4 g4 = *(const float4*)&gwr[pp];
                    acc[0][pp + 0] += f.x * g4.x; acc[0][pp + 1] += f.x * g4.y;
                    acc[0][pp + 2] += f.x * g4.z; acc[0][pp + 3] += f.x * g4.w;
                    acc[1][pp + 0] += f.y * g4.x; acc[1][pp + 1] += f.y * g4.y;
                    acc[1][pp + 2] += f.y * g4.z; acc[1][pp + 3] += f.y * g4.w;
                    acc[2][pp + 0] += f.z * g4.x; acc[2][pp + 1] += f.z * g4.y;
                    acc[2][pp + 2] += f.z * g4.z; acc[2][pp + 3] += f.z * g4.w;
                    acc[3][pp + 0] += f.w * g4.x; acc[3][pp + 1] += f.w * g4.y;
                    acc[3][pp + 2] += f.w * g4.z; acc[3][pp + 3] += f.w * g4.w;
                }
            }
        }
        __syncthreads();
    }

    // share density, normalize, single write
    s_d[t] = dacc;
    __syncthreads();
    float inv[16];
    #pragma unroll
    for (int p = 0; p < 16; p++) inv[p] = 1.0f / fmaxf(s_d[ly * 16 + p], 1e-6f);

    int gy = ty0 + ly;
    float* base = out + (((size_t)(b * CC + slice * 64 + lx * 4) * HI + gy) * WI + tx0);
    #pragma unroll
    for (int ci = 0; ci < 4; ci++) {
        float* row = base + (size_t)ci * HW;
        #pragma unroll
        for (int pp = 0; pp < 16; pp += 4) {
            float4 o = make_float4(acc[ci][pp + 0] * inv[pp + 0],
                                   acc[ci][pp + 1] * inv[pp + 1],
                                   acc[ci][pp + 2] * inv[pp + 2],
                                   acc[ci][pp + 3] * inv[pp + 3]);
            *(float4*)&row[pp] = o;
        }
    }
    if (slice == 0) {
        int pix = gy * WI + tx0 + lx;
        float d = fmaxf(dacc, 1e-6f);
        out[FM_SIZE + b * HW + pix] = uacc / d;        // uncertainty / density
        out[FM_SIZE + BB * HW + b * HW + pix] = d;     // clipped density
    }
}

// ---------------- launch ----------------
extern "C" void kernel_launch(void* const* d_in, const int* in_sizes, int n_in,
                              void* d_out, int out_size) {
    const float* g      = (const float*)d_in[0];
    const float* intr   = (const float*)d_in[1];
    const float* enc_w1 = (const float*)d_in[2];
    const float* enc_b1 = (const float*)d_in[3];
    const float* enc_w2 = (const float*)d_in[4];
    const float* enc_b2 = (const float*)d_in[5];
    const float* enc_w3 = (const float*)d_in[6];
    const float* enc_b3 = (const float*)d_in[7];
    const float* ft_w1  = (const float*)d_in[8];
    const float* ft_b1  = (const float*)d_in[9];
    const float* ft_w2  = (const float*)d_in[10];
    const float* ft_b2  = (const float*)d_in[11];
    float* out = (float*)d_out;

    float *p_h1, *p_h2, *p_feats, *p_ft1, *p_featsT;
    int* p_tcount;
    cudaGetSymbolAddress((void**)&p_h1, g_h1);
    cudaGetSymbolAddress((void**)&p_h2, g_h2);
    cudaGetSymbolAddress((void**)&p_feats, g_feats);
    cudaGetSymbolAddress((void**)&p_ft1, g_ft1);
    cudaGetSymbolAddress((void**)&p_featsT, g_featsT);
    cudaGetSymbolAddress((void**)&p_tcount, g_tcount);

    cudaMemsetAsync(p_tcount, 0, NT * sizeof(int));
    proj_bin_kernel<<<(BN + 255) / 256, 256>>>(g, intr);

    gemm_kernel<<<dim3(BN / 64, 1), 512>>>(g,        enc_w1, enc_b1, p_h1,     14,  64,  1);
    gemm_kernel<<<dim3(BN / 64, 2), 512>>>(p_h1,     enc_w2, enc_b2, p_h2,     64,  128, 1);
    gemm_kernel<<<dim3(BN / 64, 4), 512>>>(p_h2,     enc_w3, enc_b3, p_feats,  128, 256, 0);
    gemm_kernel<<<dim3(BN / 64, 4), 512>>>(p_feats,  ft_w1,  ft_b1,  p_ft1,    256, 256, 1);
    gemm_kernel<<<dim3(BN / 64, 4), 512>>>(p_ft1,    ft_w2,  ft_b2,  p_featsT, 256, 256, 0);

    render_kernel<<<dim3(NT, 4), 256>>>(out);
}

// round 10
// speedup vs baseline: 1.2443x; 1.0649x over previous
#include <cuda_runtime.h>
#include <math.h>
#include <stdint.h>

// Problem constants
#define BB 2
#define NN 2048
#define BN 4096          // B*N
#define CC 256
#define HI 64
#define WI 176
#define HW (HI*WI)       // 11264
#define TS 16            // tile size
#define TBX (WI/TS)      // 11
#define TBY (HI/TS)      // 4
#define TPB (TBX*TBY)    // 44 tiles per batch
#define NT (BB*TPB)      // 88 tiles total
#define MAXG 2048
#define FM_SIZE (BB*CC*HW)

// ---------------- device scratch ----------------
__device__ float g_h1[BN*64];
__device__ float g_h2[BN*128];
__device__ float g_feats[BN*CC];
__device__ float g_ft1[BN*CC];
__device__ float g_featsT[BN*CC];

__device__ float g_px[BN], g_py[BN], g_isx[BN], g_isy[BN], g_w[BN], g_as[BN];
__device__ int   g_tcount[NT];
__device__ int   g_tlist[NT*MAXG];

// ---------------- tf32 helpers ----------------
__device__ __forceinline__ float f2tf32(float x) {
    uint32_t r; asm("cvt.rna.tf32.f32 %0, %1;" : "=r"(r) : "f"(x));
    return __uint_as_float(r);
}
__device__ __forceinline__ void mma_tf32(float* c,
    uint32_t a0, uint32_t a1, uint32_t a2, uint32_t a3,
    uint32_t b0, uint32_t b1)
{
    asm("mma.sync.aligned.m16n8k8.row.col.f32.tf32.tf32.f32 "
        "{%0,%1,%2,%3}, {%4,%5,%6,%7}, {%8,%9}, {%0,%1,%2,%3};"
        : "+f"(c[0]), "+f"(c[1]), "+f"(c[2]), "+f"(c[3])
        : "r"(a0), "r"(a1), "r"(a2), "r"(a3), "r"(b0), "r"(b1));
}

// ---------------- projection + binning (fused) ----------------
__global__ void proj_bin_kernel(const float* __restrict__ g, const float* __restrict__ Kin) {
    int i = blockIdx.x * blockDim.x + threadIdx.x;
    if (i >= BN) return;
    const float* gd = g + (size_t)i * 14;
    float x = gd[0], y = gd[1], z = gd[2];
    float k00 = Kin[0], k01 = Kin[1], k02 = Kin[2];
    float k10 = Kin[3], k11 = Kin[4], k12 = Kin[5];
    float k20 = Kin[6], k21 = Kin[7], k22 = Kin[8];
    float pz = k20 * x + k21 * y + k22 * z;
    float denom = pz + 1e-6f;
    float pxn = (k00 * x + k01 * y + k02 * z) / denom;
    float pyn = (k10 * x + k11 * y + k12 * z) / denom;
    float scale_x = (float)WI / k02 * 0.5f;
    float scale_y = (float)HI / k12 * 0.5f;
    float px = pxn * scale_x;
    float py = pyn * scale_y;
    bool valid = (z > 0.1f);
    bool inb = (px >= 0.f) && (px < (float)WI) && (py >= 0.f) && (py < (float)HI);
    bool mask = valid && inb;
    float sx = fmaxf(gd[5] * scale_x, 1.0f);
    float sy = fmaxf(gd[6] * scale_y, 1.0f);
    float w = mask ? gd[12] : 0.0f;
    g_px[i] = px;  g_py[i] = py;
    g_isx[i] = 1.0f / sx;  g_isy[i] = 1.0f / sy;
    g_w[i]  = w;
    g_as[i] = 0.5f * (sx + sy);
    if (w == 0.0f) return;

    float rx = 3.0f * sx;
    float ry = 3.0f * sy;
    int b = i >> 11;
    int tx0 = max(0, (int)floorf((px - rx) * (1.0f / TS)));
    int tx1 = min(TBX - 1, (int)floorf((px + rx) * (1.0f / TS)));
    int ty0 = max(0, (int)floorf((py - ry) * (1.0f / TS)));
    int ty1 = min(TBY - 1, (int)floorf((py + ry) * (1.0f / TS)));
    for (int ty = ty0; ty <= ty1; ty++)
        for (int tx = tx0; tx <= tx1; tx++) {
            int t = b * TPB + ty * TBX + tx;
            int o = atomicAdd(&g_tcount[t], 1);
            if (o < MAXG) g_tlist[t * MAXG + o] = i;
        }
}

// ---------------- tf32 tensor-core GEMM with 3xTF32 split ----------------
// C[M x Nd] = act(A[M x Kd] @ W[Kd x Nd] + bias), fp32-accurate via
// a = a_hi + a_lo, b = b_hi + b_lo; D += ah*bh + al*bh + ah*bl.
// Block tile 128x64, k-tile 16, 256 threads = 8 warps in 4(M) x 2(N) grid.
// Each warp: 32x32 output = 2 m16-tiles x 4 n8-tiles of mma.m16n8k8.
__global__ void __launch_bounds__(256) gemm_tf32_kernel(
    const float* __restrict__ A, const float* __restrict__ Wm,
    const float* __restrict__ bias, float* __restrict__ Cm,
    int Kd, int Nd, int doRelu)
{
    __shared__ float Ah[16][132], Al[16][132];   // [k][m], pad -> bank (4k+m)%32
    __shared__ float Bh[16][68],  Bl[16][68];    // [k][n]

    int m0 = blockIdx.x * 128;
    int n0 = blockIdx.y * 64;
    int t = threadIdx.x;
    int lane = t & 31;
    int wid = t >> 5;
    int wm = wid & 3;        // 0..3 -> 32 M-rows each
    int wn = wid >> 2;       // 0..1 -> 32 N-cols each
    int g = lane >> 2;       // groupID 0..7
    int c = lane & 3;        // threadID-in-group 0..3

    float d[2][4][4];
    #pragma unroll
    for (int mt = 0; mt < 2; mt++)
        #pragma unroll
        for (int nt = 0; nt < 4; nt++)
            #pragma unroll
            for (int i = 0; i < 4; i++) d[mt][nt][i] = 0.f;

    int nkt = (Kd + 15) >> 4;
    bool fast = ((Kd & 15) == 0);

    for (int kt = 0; kt < nkt; kt++) {
        int kb = kt * 16;
        // ---- load + split A tile: 128 rows x 16 k (2 threads per row) ----
        {
            int row = t >> 1;
            int k0 = (t & 1) * 8;
            const float* src = &A[(size_t)(m0 + row) * Kd + kb + k0];
            float v[8];
            if (fast) {
                float4 q0 = *(const float4*)&src[0];
                float4 q1 = *(const float4*)&src[4];
                v[0]=q0.x; v[1]=q0.y; v[2]=q0.z; v[3]=q0.w;
                v[4]=q1.x; v[5]=q1.y; v[6]=q1.z; v[7]=q1.w;
            } else {
                #pragma unroll
                for (int i = 0; i < 8; i++)
                    v[i] = (kb + k0 + i < Kd) ? src[i] : 0.f;
            }
            #pragma unroll
            for (int i = 0; i < 8; i++) {
                float hi = f2tf32(v[i]);
                Ah[k0 + i][row] = hi;
                Al[k0 + i][row] = f2tf32(v[i] - hi);
            }
        }
        // ---- load + split B tile: 16 k x 64 n (one float4 per thread) ----
        {
            int kk = t >> 4;
            int n4 = (t & 15) * 4;
            float v[4];
            if (fast) {
                float4 q = *(const float4*)&Wm[(size_t)(kb + kk) * Nd + n0 + n4];
                v[0]=q.x; v[1]=q.y; v[2]=q.z; v[3]=q.w;
            } else {
                bool ok = (kb + kk < Kd);
                #pragma unroll
                for (int i = 0; i < 4; i++)
                    v[i] = ok ? Wm[(size_t)(kb + kk) * Nd + n0 + n4 + i] : 0.f;
            }
            #pragma unroll
            for (int i = 0; i < 4; i++) {
                float hi = f2tf32(v[i]);
                Bh[kk][n4 + i] = hi;
                Bl[kk][n4 + i] = f2tf32(v[i] - hi);
            }
        }
        __syncthreads();

        #pragma unroll
        for (int ks = 0; ks < 2; ks++) {
            int kk = ks * 8;
            uint32_t ah[2][4], al[2][4], bh[4][2], bl[4][2];
            #pragma unroll
            for (int mt = 0; mt < 2; mt++) {
                int m = wm * 32 + mt * 16 + g;
                ah[mt][0] = __float_as_uint(Ah[kk + c][m]);
                ah[mt][1] = __float_as_uint(Ah[kk + c][m + 8]);
                ah[mt][2] = __float_as_uint(Ah[kk + c + 4][m]);
                ah[mt][3] = __float_as_uint(Ah[kk + c + 4][m + 8]);
                al[mt][0] = __float_as_uint(Al[kk + c][m]);
                al[mt][1] = __float_as_uint(Al[kk + c][m + 8]);
                al[mt][2] = __float_as_uint(Al[kk + c + 4][m]);
                al[mt][3] = __float_as_uint(Al[kk + c + 4][m + 8]);
            }
            #pragma unroll
            for (int nt = 0; nt < 4; nt++) {
                int n = wn * 32 + nt * 8 + g;
                bh[nt][0] = __float_as_uint(Bh[kk + c][n]);
                bh[nt][1] = __float_as_uint(Bh[kk + c + 4][n]);
                bl[nt][0] = __float_as_uint(Bl[kk + c][n]);
                bl[nt][1] = __float_as_uint(Bl[kk + c + 4][n]);
            }
            #pragma unroll
            for (int mt = 0; mt < 2; mt++)
                #pragma unroll
                for (int nt = 0; nt < 4; nt++) {
                    mma_tf32(d[mt][nt], ah[mt][0], ah[mt][1], ah[mt][2], ah[mt][3],
                             bh[nt][0], bh[nt][1]);
                    mma_tf32(d[mt][nt], al[mt][0], al[mt][1], al[mt][2], al[mt][3],
                             bh[nt][0], bh[nt][1]);
                    mma_tf32(d[mt][nt], ah[mt][0], ah[mt][1], ah[mt][2], ah[mt][3],
                             bl[nt][0], bl[nt][1]);
                }
        }
        __syncthreads();
    }

    // ---- epilogue: bias + relu + store ----
    #pragma unroll
    for (int nt = 0; nt < 4; nt++) {
        int col = n0 + wn * 32 + nt * 8 + c * 2;
        float2 bv = *(const float2*)&bias[col];
        #pragma unroll
        for (int mt = 0; mt < 2; mt++) {
            int row0 = m0 + wm * 32 + mt * 16 + g;
            float2 o0 = make_float2(d[mt][nt][0] + bv.x, d[mt][nt][1] + bv.y);
            float2 o1 = make_float2(d[mt][nt][2] + bv.x, d[mt][nt][3] + bv.y);
            if (doRelu) {
                o0.x = fmaxf(o0.x, 0.f); o0.y = fmaxf(o0.y, 0.f);
                o1.x = fmaxf(o1.x, 0.f); o1.y = fmaxf(o1.y, 0.f);
            }
            *(float2*)&Cm[(size_t)row0 * Nd + col]       = o0;
            *(float2*)&Cm[(size_t)(row0 + 8) * Nd + col] = o1;
        }
    }
}

// ---------------- tile render: 4 slices x 64 ch, fused normalization ---------
__global__ void __launch_bounds__(256, 2) render_kernel(float* __restrict__ out) {
    int tile = blockIdx.x;
    int slice = blockIdx.y;
    int b = tile / TPB;
    int tl = tile % TPB;
    int tx0 = (tl % TBX) * TS;
    int ty0 = (tl / TBX) * TS;
    int t = threadIdx.x;
    int lx = t & 15;
    int ly = t >> 4;

    __shared__ float s_px[16], s_py[16], s_isx[16], s_isy[16], s_w[16], s_as[16];
    __shared__ int   s_n[16];
    __shared__ float s_ex[16][16], s_ey[16][16], s_dx2[16][16], s_dy2[16][16];
    __shared__ __align__(16) float s_gw[16][256];
    __shared__ __align__(16) float s_F[16][64];
    __shared__ float s_d[256];

    float acc[4][16];
    #pragma unroll
    for (int i = 0; i < 4; i++)
        #pragma unroll
        for (int p = 0; p < 16; p++) acc[i][p] = 0.f;
    float dacc = 0.f, uacc = 0.f;

    int K = g_tcount[tile];
    if (K > MAXG) K = MAXG;

    for (int c0 = 0; c0 < K; c0 += 16) {
        if (t < 16) {
            int idx = c0 + t;
            if (idx < K) {
                int n = g_tlist[tile * MAXG + idx];
                s_n[t] = n;
                s_px[t] = g_px[n];   s_py[t] = g_py[n];
                s_isx[t] = g_isx[n]; s_isy[t] = g_isy[n];
                s_w[t] = g_w[n];     s_as[t] = g_as[n];
            } else {
                s_n[t] = 0;
                s_px[t] = 3e8f; s_py[t] = 3e8f;
                s_isx[t] = 1.f; s_isy[t] = 1.f;
                s_w[t] = 0.f;   s_as[t] = 0.f;
            }
        }
        __syncthreads();
        {
            int j = t >> 4;
            int cc = (t & 15) * 4;
            int n = s_n[j];
            float4 f = *(const float4*)&g_featsT[(size_t)n * CC + slice * 64 + cc];
            *(float4*)&s_F[j][cc] = f;
        }
        {
            int j = t >> 4, i2 = t & 15;
            float dx = ((float)(tx0 + i2) - s_px[j]) * s_isx[j];
            float dx2 = dx * dx;
            s_dx2[j][i2] = dx2;
            s_ex[j][i2] = __expf(-0.5f * dx2);
            float dy = ((float)(ty0 + i2) - s_py[j]) * s_isy[j];
            float dy2 = dy * dy;
            s_dy2[j][i2] = dy2;
            s_ey[j][i2] = __expf(-0.5f * dy2);
        }
        __syncthreads();
        #pragma unroll
        for (int j = 0; j < 16; j++) {
            float dd = s_dx2[j][lx] + s_dy2[j][ly];
            float gwv = (dd < 9.0f) ? s_w[j] * s_ex[j][lx] * s_ey[j][ly] : 0.0f;
            s_gw[j][t] = gwv;
            dacc += gwv;
            uacc += gwv * s_as[j];
        }
        __syncthreads();
        {
            int cg = lx;
            #pragma unroll
            for (int j = 0; j < 16; j++) {
                float4 f = *(const float4*)&s_F[j][cg * 4];
                const float* gwr = &s_gw[j][ly * 16];
                #pragma unroll
                for (int pp = 0; pp < 16; pp += 4) {
                    float4 g4 = *(const float4*)&gwr[pp];
                    acc[0][pp + 0] += f.x * g4.x; acc[0][pp + 1] += f.x * g4.y;
                    acc[0][pp + 2] += f.x * g4.z; acc[0][pp + 3] += f.x * g4.w;
                    acc[1][pp + 0] += f.y * g4.x; acc[1][pp + 1] += f.y * g4.y;
                    acc[1][pp + 2] += f.y * g4.z; acc[1][pp + 3] += f.y * g4.w;
                    acc[2][pp + 0] += f.z * g4.x; acc[2][pp + 1] += f.z * g4.y;
                    acc[2][pp + 2] += f.z * g4.z; acc[2][pp + 3] += f.z * g4.w;
                    acc[3][pp + 0] += f.w * g4.x; acc[3][pp + 1] += f.w * g4.y;
                    acc[3][pp + 2] += f.w * g4.z; acc[3][pp + 3] += f.w * g4.w;
                }
            }
        }
        __syncthreads();
    }

    s_d[t] = dacc;
    __syncthreads();
    float inv[16];
    #pragma unroll
    for (int p = 0; p < 16; p++) inv[p] = 1.0f / fmaxf(s_d[ly * 16 + p], 1e-6f);

    int gy = ty0 + ly;
    float* base = out + (((size_t)(b * CC + slice * 64 + lx * 4) * HI + gy) * WI + tx0);
    #pragma unroll
    for (int ci = 0; ci < 4; ci++) {
        float* row = base + (size_t)ci * HW;
        #pragma unroll
        for (int pp = 0; pp < 16; pp += 4) {
            float4 o = make_float4(acc[ci][pp + 0] * inv[pp + 0],
                                   acc[ci][pp + 1] * inv[pp + 1],
                                   acc[ci][pp + 2] * inv[pp + 2],
                                   acc[ci][pp + 3] * inv[pp + 3]);
            *(float4*)&row[pp] = o;
        }
    }
    if (slice == 0) {
        int pix = gy * WI + tx0 + lx;
        float d = fmaxf(dacc, 1e-6f);
        out[FM_SIZE + b * HW + pix] = uacc / d;
        out[FM_SIZE + BB * HW + b * HW + pix] = d;
    }
}

// ---------------- launch ----------------
extern "C" void kernel_launch(void* const* d_in, const int* in_sizes, int n_in,
                              void* d_out, int out_size) {
    const float* g      = (const float*)d_in[0];
    const float* intr   = (const float*)d_in[1];
    const float* enc_w1 = (const float*)d_in[2];
    const float* enc_b1 = (const float*)d_in[3];
    const float* enc_w2 = (const float*)d_in[4];
    const float* enc_b2 = (const float*)d_in[5];
    const float* enc_w3 = (const float*)d_in[6];
    const float* enc_b3 = (const float*)d_in[7];
    const float* ft_w1  = (const float*)d_in[8];
    const float* ft_b1  = (const float*)d_in[9];
    const float* ft_w2  = (const float*)d_in[10];
    const float* ft_b2  = (const float*)d_in[11];
    float* out = (float*)d_out;

    float *p_h1, *p_h2, *p_feats, *p_ft1, *p_featsT;
    int* p_tcount;
    cudaGetSymbolAddress((void**)&p_h1, g_h1);
    cudaGetSymbolAddress((void**)&p_h2, g_h2);
    cudaGetSymbolAddress((void**)&p_feats, g_feats);
    cudaGetSymbolAddress((void**)&p_ft1, g_ft1);
    cudaGetSymbolAddress((void**)&p_featsT, g_featsT);
    cudaGetSymbolAddress((void**)&p_tcount, g_tcount);

    cudaMemsetAsync(p_tcount, 0, NT * sizeof(int));
    proj_bin_kernel<<<(BN + 255) / 256, 256>>>(g, intr);

    gemm_tf32_kernel<<<dim3(BN / 128, 1), 256>>>(g,       enc_w1, enc_b1, p_h1,     14,  64,  1);
    gemm_tf32_kernel<<<dim3(BN / 128, 2), 256>>>(p_h1,    enc_w2, enc_b2, p_h2,     64,  128, 1);
    gemm_tf32_kernel<<<dim3(BN / 128, 4), 256>>>(p_h2,    enc_w3, enc_b3, p_feats,  128, 256, 0);
    gemm_tf32_kernel<<<dim3(BN / 128, 4), 256>>>(p_feats, ft_w1,  ft_b1,  p_ft1,    256, 256, 1);
    gemm_tf32_kernel<<<dim3(BN / 128, 4), 256>>>(p_ft1,   ft_w2,  ft_b2,  p_featsT, 256, 256, 0);

    render_kernel<<<dim3(NT, 4), 256>>>(out);
}

// round 11
// speedup vs baseline: 1.4457x; 1.1619x over previous
#include <cuda_runtime.h>
#include <math.h>
#include <stdint.h>

// Problem constants
#define BB 2
#define NN 2048
#define BN 4096          // B*N
#define CC 256
#define HI 64
#define WI 176
#define HW (HI*WI)       // 11264
#define TS 16            // tile size
#define TBX (WI/TS)      // 11
#define TBY (HI/TS)      // 4
#define TPB (TBX*TBY)    // 44 tiles per batch
#define NT (BB*TPB)      // 88 tiles total
#define MAXG 2048
#define FM_SIZE (BB*CC*HW)

// ---------------- device scratch ----------------
__device__ float g_h1[BN*64];
__device__ float g_h2[BN*128];
__device__ float g_feats[BN*CC];
__device__ float g_ft1[BN*CC];
__device__ float g_featsT[BN*CC];

__device__ float g_px[BN], g_py[BN], g_isx[BN], g_isy[BN], g_w[BN], g_as[BN];
__device__ int   g_tcount[NT];
__device__ int   g_tlist[NT*MAXG];

// ---------------- tf32 helpers ----------------
__device__ __forceinline__ float f2tf32(float x) {
    uint32_t r; asm("cvt.rna.tf32.f32 %0, %1;" : "=r"(r) : "f"(x));
    return __uint_as_float(r);
}
__device__ __forceinline__ void mma_tf32(float* c,
    uint32_t a0, uint32_t a1, uint32_t a2, uint32_t a3,
    uint32_t b0, uint32_t b1)
{
    asm("mma.sync.aligned.m16n8k8.row.col.f32.tf32.tf32.f32 "
        "{%0,%1,%2,%3}, {%4,%5,%6,%7}, {%8,%9}, {%0,%1,%2,%3};"
        : "+f"(c[0]), "+f"(c[1]), "+f"(c[2]), "+f"(c[3])
        : "r"(a0), "r"(a1), "r"(a2), "r"(a3), "r"(b0), "r"(b1));
}

// ---------------- projection + binning (fused) ----------------
__global__ void proj_bin_kernel(const float* __restrict__ g, const float* __restrict__ Kin) {
    int i = blockIdx.x * blockDim.x + threadIdx.x;
    if (i >= BN) return;
    const float* gd = g + (size_t)i * 14;
    float x = gd[0], y = gd[1], z = gd[2];
    float k00 = Kin[0], k01 = Kin[1], k02 = Kin[2];
    float k10 = Kin[3], k11 = Kin[4], k12 = Kin[5];
    float k20 = Kin[6], k21 = Kin[7], k22 = Kin[8];
    float pz = k20 * x + k21 * y + k22 * z;
    float denom = pz + 1e-6f;
    float pxn = (k00 * x + k01 * y + k02 * z) / denom;
    float pyn = (k10 * x + k11 * y + k12 * z) / denom;
    float scale_x = (float)WI / k02 * 0.5f;
    float scale_y = (float)HI / k12 * 0.5f;
    float px = pxn * scale_x;
    float py = pyn * scale_y;
    bool valid = (z > 0.1f);
    bool inb = (px >= 0.f) && (px < (float)WI) && (py >= 0.f) && (py < (float)HI);
    bool mask = valid && inb;
    float sx = fmaxf(gd[5] * scale_x, 1.0f);
    float sy = fmaxf(gd[6] * scale_y, 1.0f);
    float w = mask ? gd[12] : 0.0f;
    g_px[i] = px;  g_py[i] = py;
    g_isx[i] = 1.0f / sx;  g_isy[i] = 1.0f / sy;
    g_w[i]  = w;
    g_as[i] = 0.5f * (sx + sy);
    if (w == 0.0f) return;

    float rx = 3.0f * sx;
    float ry = 3.0f * sy;
    int b = i >> 11;
    int tx0 = max(0, (int)floorf((px - rx) * (1.0f / TS)));
    int tx1 = min(TBX - 1, (int)floorf((px + rx) * (1.0f / TS)));
    int ty0 = max(0, (int)floorf((py - ry) * (1.0f / TS)));
    int ty1 = min(TBY - 1, (int)floorf((py + ry) * (1.0f / TS)));
    for (int ty = ty0; ty <= ty1; ty++)
        for (int tx = tx0; tx <= tx1; tx++) {
            int t = b * TPB + ty * TBX + tx;
            int o = atomicAdd(&g_tcount[t], 1);
            if (o < MAXG) g_tlist[t * MAXG + o] = i;
        }
}

// ---------------- tf32 GEMM: 64x64 tile, double-buffered, 3xTF32 ----------------
// 256 threads = 8 warps, 2(M)x4(N) warp grid, warp tile 32x16.
// Loop: convert(buf) -> sync -> prefetch(kt+1) -> mma(buf). One sync per k-tile.
__global__ void __launch_bounds__(256) gemm_tf32_kernel(
    const float* __restrict__ A, const float* __restrict__ Wm,
    const float* __restrict__ bias, float* __restrict__ Cm,
    int Kd, int Nd, int doRelu)
{
    __shared__ float Ah[2][16][72], Al[2][16][72];   // [k][m], stride 72 -> conflict-free frags
    __shared__ float Bh[2][16][72], Bl[2][16][72];   // [k][n]

    int m0 = blockIdx.x * 64;
    int n0 = blockIdx.y * 64;
    int t = threadIdx.x;
    int lane = t & 31;
    int wid = t >> 5;
    int wm = wid & 1;        // 2 warps in M (32 rows each)
    int wn = wid >> 1;       // 4 warps in N (16 cols each)
    int g = lane >> 2;
    int c = lane & 3;

    float d[2][2][4];
    #pragma unroll
    for (int mt = 0; mt < 2; mt++)
        #pragma unroll
        for (int nt = 0; nt < 2; nt++)
            #pragma unroll
            for (int i = 0; i < 4; i++) d[mt][nt][i] = 0.f;

    int nkt = (Kd + 15) >> 4;
    bool fast = ((Kd & 15) == 0);

    int arow = t >> 2, ak0 = (t & 3) * 4;   // A: 64 rows x 16 k, float4/thread
    int bkk = t >> 4, bn4 = (t & 15) * 4;   // B: 16 k x 64 n, float4/thread

    float av[4], bv[4];
    // prefetch k-tile 0
    if (fast) {
        float4 q = *(const float4*)&A[(size_t)(m0 + arow) * Kd + ak0];
        av[0]=q.x; av[1]=q.y; av[2]=q.z; av[3]=q.w;
        float4 w = *(const float4*)&Wm[(size_t)bkk * Nd + n0 + bn4];
        bv[0]=w.x; bv[1]=w.y; bv[2]=w.z; bv[3]=w.w;
    } else {
        #pragma unroll
        for (int i = 0; i < 4; i++)
            av[i] = (ak0 + i < Kd) ? A[(size_t)(m0 + arow) * Kd + ak0 + i] : 0.f;
        bool ok = (bkk < Kd);
        #pragma unroll
        for (int i = 0; i < 4; i++)
            bv[i] = ok ? Wm[(size_t)bkk * Nd + n0 + bn4 + i] : 0.f;
    }

    for (int kt = 0; kt < nkt; kt++) {
        int buf = kt & 1;
        // convert + store to smem
        #pragma unroll
        for (int i = 0; i < 4; i++) {
            float hi = f2tf32(av[i]);
            Ah[buf][ak0 + i][arow] = hi;
            Al[buf][ak0 + i][arow] = f2tf32(av[i] - hi);
        }
        #pragma unroll
        for (int i = 0; i < 4; i++) {
            float hi = f2tf32(bv[i]);
            Bh[buf][bkk][bn4 + i] = hi;
            Bl[buf][bkk][bn4 + i] = f2tf32(bv[i] - hi);
        }
        __syncthreads();
        // prefetch next k-tile (overlaps with mma below)
        if (kt + 1 < nkt) {
            int kb = (kt + 1) * 16;
            if (fast) {
                float4 q = *(const float4*)&A[(size_t)(m0 + arow) * Kd + kb + ak0];
                av[0]=q.x; av[1]=q.y; av[2]=q.z; av[3]=q.w;
                float4 w = *(const float4*)&Wm[(size_t)(kb + bkk) * Nd + n0 + bn4];
                bv[0]=w.x; bv[1]=w.y; bv[2]=w.z; bv[3]=w.w;
            } else {
                #pragma unroll
                for (int i = 0; i < 4; i++)
                    av[i] = (kb + ak0 + i < Kd) ? A[(size_t)(m0 + arow) * Kd + kb + ak0 + i] : 0.f;
                bool ok = (kb + bkk < Kd);
                #pragma unroll
                for (int i = 0; i < 4; i++)
                    bv[i] = ok ? Wm[(size_t)(kb + bkk) * Nd + n0 + bn4 + i] : 0.f;
            }
        }
        // mma on buf
        #pragma unroll
        for (int ks = 0; ks < 2; ks++) {
            int kk = ks * 8;
            uint32_t ah[2][4], al[2][4], bh[2][2], bl[2][2];
            #pragma unroll
            for (int mt = 0; mt < 2; mt++) {
                int m = wm * 32 + mt * 16 + g;
                ah[mt][0] = __float_as_uint(Ah[buf][kk + c][m]);
                ah[mt][1] = __float_as_uint(Ah[buf][kk + c][m + 8]);
                ah[mt][2] = __float_as_uint(Ah[buf][kk + c + 4][m]);
                ah[mt][3] = __float_as_uint(Ah[buf][kk + c + 4][m + 8]);
                al[mt][0] = __float_as_uint(Al[buf][kk + c][m]);
                al[mt][1] = __float_as_uint(Al[buf][kk + c][m + 8]);
                al[mt][2] = __float_as_uint(Al[buf][kk + c + 4][m]);
                al[mt][3] = __float_as_uint(Al[buf][kk + c + 4][m + 8]);
            }
            #pragma unroll
            for (int nt = 0; nt < 2; nt++) {
                int n = wn * 16 + nt * 8 + g;
                bh[nt][0] = __float_as_uint(Bh[buf][kk + c][n]);
                bh[nt][1] = __float_as_uint(Bh[buf][kk + c + 4][n]);
                bl[nt][0] = __float_as_uint(Bl[buf][kk + c][n]);
                bl[nt][1] = __float_as_uint(Bl[buf][kk + c + 4][n]);
            }
            #pragma unroll
            for (int mt = 0; mt < 2; mt++)
                #pragma unroll
                for (int nt = 0; nt < 2; nt++) {
                    mma_tf32(d[mt][nt], ah[mt][0], ah[mt][1], ah[mt][2], ah[mt][3],
                             bh[nt][0], bh[nt][1]);
                    mma_tf32(d[mt][nt], al[mt][0], al[mt][1], al[mt][2], al[mt][3],
                             bh[nt][0], bh[nt][1]);
                    mma_tf32(d[mt][nt], ah[mt][0], ah[mt][1], ah[mt][2], ah[mt][3],
                             bl[nt][0], bl[nt][1]);
                }
        }
    }

    // epilogue
    #pragma unroll
    for (int nt = 0; nt < 2; nt++) {
        int col = n0 + wn * 16 + nt * 8 + c * 2;
        float2 bv2 = *(const float2*)&bias[col];
        #pragma unroll
        for (int mt = 0; mt < 2; mt++) {
            int row0 = m0 + wm * 32 + mt * 16 + g;
            float2 o0 = make_float2(d[mt][nt][0] + bv2.x, d[mt][nt][1] + bv2.y);
            float2 o1 = make_float2(d[mt][nt][2] + bv2.x, d[mt][nt][3] + bv2.y);
            if (doRelu) {
                o0.x = fmaxf(o0.x, 0.f); o0.y = fmaxf(o0.y, 0.f);
                o1.x = fmaxf(o1.x, 0.f); o1.y = fmaxf(o1.y, 0.f);
            }
            *(float2*)&Cm[(size_t)row0 * Nd + col]       = o0;
            *(float2*)&Cm[(size_t)(row0 + 8) * Nd + col] = o1;
        }
    }
}

// ---------------- tile render: tensor-core feature accumulate -----------------
// grid (NT, 4 slices), 256 threads = 8 warps in 2(ch) x 4(px) grid.
// Per 16-gaussian batch: Out[64ch][256px] += F^T[16][64] @ Gw[16][256]
// via 3xTF32 m16n8k8. Density/uncertainty stay exact fp32. Fused normalization.
__global__ void __launch_bounds__(256, 2) render_kernel(float* __restrict__ out) {
    int tile = blockIdx.x;
    int slice = blockIdx.y;
    int b = tile / TPB;
    int tl = tile % TPB;
    int tx0 = (tl % TBX) * TS;
    int ty0 = (tl / TBX) * TS;
    int t = threadIdx.x;
    int lx = t & 15;
    int ly = t >> 4;
    int lane = t & 31;
    int wid = t >> 5;
    int wm = wid & 1;        // 2 warps in M=channels (32 each)
    int wn = wid >> 1;       // 4 warps in N=pixels (64 each)
    int g = lane >> 2;
    int c = lane & 3;

    __shared__ float s_px[16], s_py[16], s_isx[16], s_isy[16], s_w[16], s_as[16];
    __shared__ int   s_n[16];
    __shared__ float s_dx2[16][16], s_dy2[16][16], s_ex[16][16], s_ey[16][16];
    __shared__ float s_gwh[16][264], s_gwl[16][264];   // stride 264 -> conflict-free frags
    __shared__ float s_Fh[16][72], s_Fl[16][72];

    float* s_d = &s_dx2[0][0];   // reuse after main loop (256 floats)

    float d[2][8][4];   // mt x nt x frag
    #pragma unroll
    for (int mt = 0; mt < 2; mt++)
        #pragma unroll
        for (int nt = 0; nt < 8; nt++)
            #pragma unroll
            for (int i = 0; i < 4; i++) d[mt][nt][i] = 0.f;
    float dacc = 0.f, uacc = 0.f;

    int K = g_tcount[tile];
    if (K > MAXG) K = MAXG;

    for (int c0 = 0; c0 < K; c0 += 16) {
        if (t < 16) {
            int idx = c0 + t;
            if (idx < K) {
                int n = g_tlist[tile * MAXG + idx];
                s_n[t] = n;
                s_px[t] = g_px[n];   s_py[t] = g_py[n];
                s_isx[t] = g_isx[n]; s_isy[t] = g_isy[n];
                s_w[t] = g_w[n];     s_as[t] = g_as[n];
            } else {
                s_n[t] = 0;
                s_px[t] = 3e8f; s_py[t] = 3e8f;
                s_isx[t] = 1.f; s_isy[t] = 1.f;
                s_w[t] = 0.f;   s_as[t] = 0.f;
            }
        }
        __syncthreads();
        // F slice: 16 gaussians x 64 channels, split hi/lo (one float4/thread)
        {
            int j = t >> 4;
            int ci = (t & 15) * 4;
            int n = s_n[j];
            float4 f = *(const float4*)&g_featsT[(size_t)n * CC + slice * 64 + ci];
            float h0 = f2tf32(f.x), h1 = f2tf32(f.y), h2 = f2tf32(f.z), h3 = f2tf32(f.w);
            s_Fh[j][ci + 0] = h0; s_Fl[j][ci + 0] = f2tf32(f.x - h0);
            s_Fh[j][ci + 1] = h1; s_Fl[j][ci + 1] = f2tf32(f.y - h1);
            s_Fh[j][ci + 2] = h2; s_Fl[j][ci + 2] = f2tf32(f.z - h2);
            s_Fh[j][ci + 3] = h3; s_Fl[j][ci + 3] = f2tf32(f.w - h3);
        }
        // separable exp
        {
            int j = t >> 4, i2 = t & 15;
            float dx = ((float)(tx0 + i2) - s_px[j]) * s_isx[j];
            float dx2 = dx * dx;
            s_dx2[j][i2] = dx2;
            s_ex[j][i2] = __expf(-0.5f * dx2);
            float dy = ((float)(ty0 + i2) - s_py[j]) * s_isy[j];
            float dy2 = dy * dy;
            s_dy2[j][i2] = dy2;
            s_ey[j][i2] = __expf(-0.5f * dy2);
        }
        __syncthreads();
        // gw for my pixel across 16 gaussians (exact fp32 density), split to tf32
        #pragma unroll
        for (int j = 0; j < 16; j++) {
            float dd = s_dx2[j][lx] + s_dy2[j][ly];
            float gwv = (dd < 9.0f) ? s_w[j] * s_ex[j][lx] * s_ey[j][ly] : 0.0f;
            float hi = f2tf32(gwv);
            s_gwh[j][t] = hi;
            s_gwl[j][t] = f2tf32(gwv - hi);
            dacc += gwv;
            uacc += gwv * s_as[j];
        }
        __syncthreads();
        // tensor-core accumulate: 2 ks x 2 mt x 8 nt x 3 splits
        #pragma unroll
        for (int ks = 0; ks < 2; ks++) {
            int kk = ks * 8;
            uint32_t ah[2][4], al[2][4];
            #pragma unroll
            for (int mt = 0; mt < 2; mt++) {
                int m = wm * 32 + mt * 16 + g;
                ah[mt][0] = __float_as_uint(s_Fh[kk + c][m]);
                ah[mt][1] = __float_as_uint(s_Fh[kk + c][m + 8]);
                ah[mt][2] = __float_as_uint(s_Fh[kk + c + 4][m]);
                ah[mt][3] = __float_as_uint(s_Fh[kk + c + 4][m + 8]);
                al[mt][0] = __float_as_uint(s_Fl[kk + c][m]);
                al[mt][1] = __float_as_uint(s_Fl[kk + c][m + 8]);
                al[mt][2] = __float_as_uint(s_Fl[kk + c + 4][m]);
                al[mt][3] = __float_as_uint(s_Fl[kk + c + 4][m + 8]);
            }
            #pragma unroll
            for (int nt = 0; nt < 8; nt++) {
                int n = wn * 64 + nt * 8 + g;
                uint32_t bh0 = __float_as_uint(s_gwh[kk + c][n]);
                uint32_t bh1 = __float_as_uint(s_gwh[kk + c + 4][n]);
                uint32_t bl0 = __float_as_uint(s_gwl[kk + c][n]);
                uint32_t bl1 = __float_as_uint(s_gwl[kk + c + 4][n]);
                #pragma unroll
                for (int mt = 0; mt < 2; mt++) {
                    mma_tf32(d[mt][nt], ah[mt][0], ah[mt][1], ah[mt][2], ah[mt][3], bh0, bh1);
                    mma_tf32(d[mt][nt], al[mt][0], al[mt][1], al[mt][2], al[mt][3], bh0, bh1);
                    mma_tf32(d[mt][nt], ah[mt][0], ah[mt][1], ah[mt][2], ah[mt][3], bl0, bl1);
                }
            }
        }
        __syncthreads();
    }

    // density to smem (s_d aliases s_dx2; safe after final sync)
    s_d[t] = dacc;
    __syncthreads();

    // normalize + write features: rows = channels, cols = pixels
    #pragma unroll
    for (int nt = 0; nt < 8; nt++) {
        int n = wn * 64 + nt * 8 + c * 2;     // pixel linear index (py*16+px)
        float inv0 = 1.0f / fmaxf(s_d[n], 1e-6f);
        float inv1 = 1.0f / fmaxf(s_d[n + 1], 1e-6f);
        int py = n >> 4;
        int pxx = n & 15;
        #pragma unroll
        for (int mt = 0; mt < 2; mt++) {
            int ch = slice * 64 + wm * 32 + mt * 16 + g;
            float* r0 = out + (((size_t)(b * CC + ch) * HI + ty0 + py) * WI + tx0 + pxx);
            float* r1 = out + (((size_t)(b * CC + ch + 8) * HI + ty0 + py) * WI + tx0 + pxx);
            *(float2*)r0 = make_float2(d[mt][nt][0] * inv0, d[mt][nt][1] * inv1);
            *(float2*)r1 = make_float2(d[mt][nt][2] * inv0, d[mt][nt][3] * inv1);
        }
    }
    if (slice == 0) {
        int pix = (ty0 + ly) * WI + tx0 + lx;
        float dv = fmaxf(dacc, 1e-6f);
        out[FM_SIZE + b * HW + pix] = uacc / dv;
        out[FM_SIZE + BB * HW + b * HW + pix] = dv;
    }
}

// ---------------- launch ----------------
extern "C" void kernel_launch(void* const* d_in, const int* in_sizes, int n_in,
                              void* d_out, int out_size) {
    const float* g      = (const float*)d_in[0];
    const float* intr   = (const float*)d_in[1];
    const float* enc_w1 = (const float*)d_in[2];
    const float* enc_b1 = (const float*)d_in[3];
    const float* enc_w2 = (const float*)d_in[4];
    const float* enc_b2 = (const float*)d_in[5];
    const float* enc_w3 = (const float*)d_in[6];
    const float* enc_b3 = (const float*)d_in[7];
    const float* ft_w1  = (const float*)d_in[8];
    const float* ft_b1  = (const float*)d_in[9];
    const float* ft_w2  = (const float*)d_in[10];
    const float* ft_b2  = (const float*)d_in[11];
    float* out = (float*)d_out;

    float *p_h1, *p_h2, *p_feats, *p_ft1, *p_featsT;
    int* p_tcount;
    cudaGetSymbolAddress((void**)&p_h1, g_h1);
    cudaGetSymbolAddress((void**)&p_h2, g_h2);
    cudaGetSymbolAddress((void**)&p_feats, g_feats);
    cudaGetSymbolAddress((void**)&p_ft1, g_ft1);
    cudaGetSymbolAddress((void**)&p_featsT, g_featsT);
    cudaGetSymbolAddress((void**)&p_tcount, g_tcount);

    cudaMemsetAsync(p_tcount, 0, NT * sizeof(int));
    proj_bin_kernel<<<(BN + 255) / 256, 256>>>(g, intr);

    gemm_tf32_kernel<<<dim3(BN / 64, 1), 256>>>(g,       enc_w1, enc_b1, p_h1,     14,  64,  1);
    gemm_tf32_kernel<<<dim3(BN / 64, 2), 256>>>(p_h1,    enc_w2, enc_b2, p_h2,     64,  128, 1);
    gemm_tf32_kernel<<<dim3(BN / 64, 4), 256>>>(p_h2,    enc_w3, enc_b3, p_feats,  128, 256, 0);
    gemm_tf32_kernel<<<dim3(BN / 64, 4), 256>>>(p_feats, ft_w1,  ft_b1,  p_ft1,    256, 256, 1);
    gemm_tf32_kernel<<<dim3(BN / 64, 4), 256>>>(p_ft1,   ft_w2,  ft_b2,  p_featsT, 256, 256, 0);

    render_kernel<<<dim3(NT, 4), 256>>>(out);
}